// round 9
// baseline (speedup 1.0000x reference)
#include <cuda_runtime.h>

typedef unsigned long long u64;
typedef unsigned int u32;

#define B 32
#define N 2048
#define C 64
#define R 32
#define K 64

__device__ float g_vals[B * K];
__device__ int   g_idx[B * K];

// Monotone key: descending value, ascending index, as one u64 (bigger = first).
__device__ __forceinline__ u64 make_key(float v, int idx) {
    u32 u = __float_as_uint(v);
    u = (u & 0x80000000u) ? ~u : (u | 0x80000000u);   // order-preserving f32->u32
    return ((u64)u << 32) | (u32)(N - 1 - idx);       // low word: smaller idx wins
}

// compare-exchange on packed keys; partner differs in lane bit j
__device__ __forceinline__ void cmpx64(u64& k, int j, bool desc) {
    u64 o = __shfl_xor_sync(0xffffffffu, k, j);
    bool keep_big = (((threadIdx.x & 31) & j) == 0) == desc;
    k = ((k > o) == keep_big) ? k : o;
}

// ---------------------------------------------------------------------------
// Kernel A (side stream): warp-register bitonic top-K on packed u64 keys.
// One block per batch row. Runs concurrently with zero_kernel.
// ---------------------------------------------------------------------------
__global__ __launch_bounds__(1024)
void topk_kernel(const float* __restrict__ acc, float* __restrict__ out) {
    __shared__ u64 sk[N];
    const int b    = blockIdx.x;
    const int tid  = threadIdx.x;
    const int lane = tid & 31;
    const int w    = tid >> 5;           // warp 0..31

    // ---- load chunk w: elements e0=lane, e1=lane+32 of a 64-elem list ----
    const float* row = acc + b * N;
    u64 k0 = make_key(row[w * 64 + lane],      w * 64 + lane);
    u64 k1 = make_key(row[w * 64 + 32 + lane], w * 64 + 32 + lane);

    // ---- bitonic sort 64 keys in-warp (descending) ----
    #pragma unroll
    for (int k = 2; k <= 32; k <<= 1) {
        #pragma unroll
        for (int j = k >> 1; j >= 1; j >>= 1) {
            cmpx64(k0, j, ((lane)      & k) == 0);
            cmpx64(k1, j, ((lane + 32) & k) == 0);
        }
    }
    // k = 64 level: j=32 is a register swap (descending)
    if (!(k0 > k1)) { u64 t = k0; k0 = k1; k1 = t; }
    #pragma unroll
    for (int j = 16; j >= 1; j >>= 1) { cmpx64(k0, j, true); cmpx64(k1, j, true); }

    sk[w * 64 + lane]      = k0;
    sk[w * 64 + 32 + lane] = k1;
    __syncthreads();

    // ---- 5 merge rounds; final round emits from warp-0 registers ----
    u64 f0 = 0, f1 = 0;
    #pragma unroll
    for (int t = 0; t < 5; t++) {
        const int nw = 16 >> t;
        if (w < nw) {
            const int la = 2 * w, lb = 2 * w + 1;
            u64 a0 = sk[la * 64 + lane];
            u64 a1 = sk[la * 64 + 32 + lane];
            u64 b0 = sk[lb * 64 + lane];
            u64 b1 = sk[lb * 64 + 32 + lane];
            u64 m0 = __shfl_xor_sync(0xffffffffu, b1, 31);
            u64 m1 = __shfl_xor_sync(0xffffffffu, b0, 31);
            if (m0 > a0) a0 = m0;
            if (m1 > a1) a1 = m1;
            if (!(a0 > a1)) { u64 tt = a0; a0 = a1; a1 = tt; }
            #pragma unroll
            for (int j = 16; j >= 1; j >>= 1) { cmpx64(a0, j, true); cmpx64(a1, j, true); }
            if (t < 4) {
                sk[w * 64 + lane]      = a0;
                sk[w * 64 + 32 + lane] = a1;
            } else { f0 = a0; f1 = a1; }
        }
        if (t < 4) __syncthreads();
    }

    if (w == 0) {
        #pragma unroll
        for (int h = 0; h < 2; h++) {
            u64 kk = h ? f1 : f0;
            int pos = lane + h * 32;
            int id = (N - 1) - (int)(kk & 0xffffffffu);
            u32 hu = (u32)(kk >> 32);
            u32 fb = (hu & 0x80000000u) ? (hu ^ 0x80000000u) : ~hu;
            float v = __uint_as_float(fb);
            out[b * K + pos]         = v;           // topk_vals
            out[B * K + b * K + pos] = (float)id;   // topk_idx
            g_vals[b * K + pos] = v;
            g_idx [b * K + pos] = id;
        }
    }
}

// ---------------------------------------------------------------------------
// Kernel B (side stream): frob — one warp per (channel, batch).
// ---------------------------------------------------------------------------
__global__ __launch_bounds__(32)
void frob_kernel(const float* __restrict__ U, float* __restrict__ out) {
    const int c = blockIdx.x;
    const int b = blockIdx.y;
    const int r = threadIdx.x;   // lane = rank index

    float v0 = g_vals[b * K + r];
    float v1 = g_vals[b * K + 32 + r];
    int   i0 = g_idx [b * K + r];
    int   i1 = g_idx [b * K + 32 + r];

    const float* Uc = U + (size_t)c * N * R;
    float au = 0.0f;
    #pragma unroll
    for (int k = 0; k < 32; k++) {
        float vk = __shfl_sync(0xffffffffu, v0, k);
        int   ik = __shfl_sync(0xffffffffu, i0, k);
        au = fmaf(vk, __ldg(Uc + (size_t)ik * R + r), au);
    }
    #pragma unroll
    for (int k = 0; k < 32; k++) {
        float vk = __shfl_sync(0xffffffffu, v1, k);
        int   ik = __shfl_sync(0xffffffffu, i1, k);
        au = fmaf(vk, __ldg(Uc + (size_t)ik * R + r), au);
    }

    float sq = au * au;
    #pragma unroll
    for (int o = 16; o > 0; o >>= 1)
        sq += __shfl_xor_sync(0xffffffffu, sq, o);
    if (r == 0) out[2 * B * K + b * C + c] = sq / (float)(K * R);
}

// ---------------------------------------------------------------------------
// Kernel C (stream 0, starts at t=0): zero the full 512 MiB of M.
// Pure streaming stores, no dependencies. 4096 blocks x 256 threads,
// 32 coalesced float4 stores per thread. Ends with launch_dependents (PDL).
// ---------------------------------------------------------------------------
__global__ __launch_bounds__(256)
void zero_kernel(float* __restrict__ outM) {
    const size_t t = (size_t)blockIdx.x * 256 + threadIdx.x;   // 0 .. 2^20-1
    float4* out4 = reinterpret_cast<float4*>(outM);
    const float4 z = make_float4(0.f, 0.f, 0.f, 0.f);
    #pragma unroll
    for (int u = 0; u < 32; u++)
        __stcs(&out4[(size_t)u * (1u << 20) + t], z);
    asm volatile("griddepcontrol.launch_dependents;");
}

// ---------------------------------------------------------------------------
// Kernel D (stream 0, PDL-dependent on zero_kernel, event-ordered after topk):
// scatter M[b, idx_i, idx_j] = v_i * v_j. grid (8, B) x 512 threads, 1/thread.
// ---------------------------------------------------------------------------
__global__ __launch_bounds__(512)
void scatter_kernel(float* __restrict__ outM) {
    __shared__ float s_vals[K];
    __shared__ int   s_idx[K];
    const int b   = blockIdx.y;
    const int tid = threadIdx.x;

    if (tid < K) { s_vals[tid] = g_vals[b * K + tid]; s_idx[tid] = g_idx[b * K + tid]; }
    __syncthreads();

    // zero_kernel's grid must be fully complete (stores visible) before overwrite.
    asm volatile("griddepcontrol.wait;" ::: "memory");

    const int p = blockIdx.x * 512 + tid;   // 0 .. 4095
    const int i = p >> 6, j = p & 63;
    outM[(size_t)b * N * N + (size_t)s_idx[i] * N + s_idx[j]] = s_vals[i] * s_vals[j];
}

// Side stream + events (host resources only — no device memory).
static cudaStream_t g_s_side;
static cudaEvent_t  g_ev_fork, g_ev_topk, g_ev_side;
struct _StreamInit {
    _StreamInit() {
        cudaStreamCreateWithFlags(&g_s_side, cudaStreamNonBlocking);
        cudaEventCreateWithFlags(&g_ev_fork, cudaEventDisableTiming);
        cudaEventCreateWithFlags(&g_ev_topk, cudaEventDisableTiming);
        cudaEventCreateWithFlags(&g_ev_side, cudaEventDisableTiming);
    }
};
static _StreamInit g_stream_init;

extern "C" void kernel_launch(void* const* d_in, const int* in_sizes, int n_in,
                              void* d_out, int out_size) {
    const float* acc = (const float*)d_in[0];   // [B, N] float32
    const float* U   = (const float*)d_in[1];   // [C, N, R] float32
    float* out  = (float*)d_out;
    float* outM = out + 3 * B * K;

    // Fork handshake FIRST (before zero_kernel) so the side stream does not
    // inherit a dependency on the 77us fill — this is the legal capture fork.
    cudaEventRecord(g_ev_fork, (cudaStream_t)0);
    cudaStreamWaitEvent(g_s_side, g_ev_fork, 0);

    // Stream 0: big zero fill starts immediately.
    zero_kernel<<<4096, 256>>>(outM);

    // Side stream: topk -> frob, concurrent with zero_kernel.
    topk_kernel<<<B, 1024, 0, g_s_side>>>(acc, out);
    cudaEventRecord(g_ev_topk, g_s_side);
    frob_kernel<<<dim3(C, B), 32, 0, g_s_side>>>(U, out);
    cudaEventRecord(g_ev_side, g_s_side);

    // Stream 0: scatter after zero (PDL) and after topk (event).
    cudaStreamWaitEvent((cudaStream_t)0, g_ev_topk, 0);
    cudaLaunchConfig_t cfg = {};
    cfg.gridDim  = dim3(8, B);
    cfg.blockDim = dim3(512);
    cfg.dynamicSmemBytes = 0;
    cfg.stream = (cudaStream_t)0;
    cudaLaunchAttribute attr[1];
    attr[0].id = cudaLaunchAttributeProgrammaticStreamSerialization;
    attr[0].val.programmaticStreamSerializationAllowed = 1;
    cfg.attrs = attr;
    cfg.numAttrs = 1;
    cudaLaunchKernelEx(&cfg, scatter_kernel, outM);

    // Join frob into stream 0.
    cudaStreamWaitEvent((cudaStream_t)0, g_ev_side, 0);
}

// round 10
// speedup vs baseline: 1.0039x; 1.0039x over previous
#include <cuda_runtime.h>

typedef unsigned long long u64;
typedef unsigned int u32;

#define B 32
#define N 2048
#define C 64
#define R 32
#define K 64

__device__ float g_pv[B * N];     // dense top-k vector per batch
__device__ float g_vals[B * K];
__device__ int   g_idx[B * K];

// Monotone key: descending value, ascending index, as one u64 (bigger = first).
__device__ __forceinline__ u64 make_key(float v, int idx) {
    u32 u = __float_as_uint(v);
    u = (u & 0x80000000u) ? ~u : (u | 0x80000000u);   // order-preserving f32->u32
    return ((u64)u << 32) | (u32)(N - 1 - idx);       // low word: smaller idx wins
}

// compare-exchange on packed keys; partner differs in lane bit j
__device__ __forceinline__ void cmpx64(u64& k, int j, bool desc) {
    u64 o = __shfl_xor_sync(0xffffffffu, k, j);
    bool keep_big = (((threadIdx.x & 31) & j) == 0) == desc;
    k = ((k > o) == keep_big) ? k : o;
}

// ---------------------------------------------------------------------------
// Kernel A (side stream): warp-register bitonic top-K + pv scatter.
// One block per batch row. Runs concurrently with zero_kernel.
// ---------------------------------------------------------------------------
__global__ __launch_bounds__(1024)
void topk_kernel(const float* __restrict__ acc, float* __restrict__ out) {
    __shared__ u64 sk[N];
    const int b    = blockIdx.x;
    const int tid  = threadIdx.x;
    const int lane = tid & 31;
    const int w    = tid >> 5;           // warp 0..31

    // zero pv row (independent of the sort)
    g_pv[b * N + tid] = 0.0f;
    g_pv[b * N + tid + 1024] = 0.0f;

    // ---- load chunk w: elements e0=lane, e1=lane+32 of a 64-elem list ----
    const float* row = acc + b * N;
    u64 k0 = make_key(row[w * 64 + lane],      w * 64 + lane);
    u64 k1 = make_key(row[w * 64 + 32 + lane], w * 64 + 32 + lane);

    // ---- bitonic sort 64 keys in-warp (descending) ----
    #pragma unroll
    for (int k = 2; k <= 32; k <<= 1) {
        #pragma unroll
        for (int j = k >> 1; j >= 1; j >>= 1) {
            cmpx64(k0, j, ((lane)      & k) == 0);
            cmpx64(k1, j, ((lane + 32) & k) == 0);
        }
    }
    // k = 64 level: j=32 is a register swap (descending)
    if (!(k0 > k1)) { u64 t = k0; k0 = k1; k1 = t; }
    #pragma unroll
    for (int j = 16; j >= 1; j >>= 1) { cmpx64(k0, j, true); cmpx64(k1, j, true); }

    sk[w * 64 + lane]      = k0;
    sk[w * 64 + 32 + lane] = k1;
    __syncthreads();

    // ---- 5 merge rounds; final round emits from warp-0 registers ----
    u64 f0 = 0, f1 = 0;
    #pragma unroll
    for (int t = 0; t < 5; t++) {
        const int nw = 16 >> t;
        if (w < nw) {
            const int la = 2 * w, lb = 2 * w + 1;
            u64 a0 = sk[la * 64 + lane];
            u64 a1 = sk[la * 64 + 32 + lane];
            u64 b0 = sk[lb * 64 + lane];
            u64 b1 = sk[lb * 64 + 32 + lane];
            u64 m0 = __shfl_xor_sync(0xffffffffu, b1, 31);
            u64 m1 = __shfl_xor_sync(0xffffffffu, b0, 31);
            if (m0 > a0) a0 = m0;
            if (m1 > a1) a1 = m1;
            if (!(a0 > a1)) { u64 tt = a0; a0 = a1; a1 = tt; }
            #pragma unroll
            for (int j = 16; j >= 1; j >>= 1) { cmpx64(a0, j, true); cmpx64(a1, j, true); }
            if (t < 4) {
                sk[w * 64 + lane]      = a0;
                sk[w * 64 + 32 + lane] = a1;
            } else { f0 = a0; f1 = a1; }
        }
        if (t < 4) __syncthreads();
    }

    if (w == 0) {
        #pragma unroll
        for (int h = 0; h < 2; h++) {
            u64 kk = h ? f1 : f0;
            int pos = lane + h * 32;
            int id = (N - 1) - (int)(kk & 0xffffffffu);
            u32 hu = (u32)(kk >> 32);
            u32 fb = (hu & 0x80000000u) ? (hu ^ 0x80000000u) : ~hu;
            float v = __uint_as_float(fb);
            out[b * K + pos]         = v;           // topk_vals
            out[B * K + b * K + pos] = (float)id;   // topk_idx
            g_vals[b * K + pos] = v;
            g_idx [b * K + pos] = id;
            g_pv  [b * N + id]  = v;
        }
    }
}

// ---------------------------------------------------------------------------
// Kernel B (side stream): frob — one warp per (channel, batch).
// ---------------------------------------------------------------------------
__global__ __launch_bounds__(32)
void frob_kernel(const float* __restrict__ U, float* __restrict__ out) {
    const int c = blockIdx.x;
    const int b = blockIdx.y;
    const int r = threadIdx.x;   // lane = rank index

    float v0 = g_vals[b * K + r];
    float v1 = g_vals[b * K + 32 + r];
    int   i0 = g_idx [b * K + r];
    int   i1 = g_idx [b * K + 32 + r];

    const float* Uc = U + (size_t)c * N * R;
    float au = 0.0f;
    #pragma unroll
    for (int k = 0; k < 32; k++) {
        float vk = __shfl_sync(0xffffffffu, v0, k);
        int   ik = __shfl_sync(0xffffffffu, i0, k);
        au = fmaf(vk, __ldg(Uc + (size_t)ik * R + r), au);
    }
    #pragma unroll
    for (int k = 0; k < 32; k++) {
        float vk = __shfl_sync(0xffffffffu, v1, k);
        int   ik = __shfl_sync(0xffffffffu, i1, k);
        au = fmaf(vk, __ldg(Uc + (size_t)ik * R + r), au);
    }

    float sq = au * au;
    #pragma unroll
    for (int o = 16; o > 0; o >>= 1)
        sq += __shfl_xor_sync(0xffffffffu, sq, o);
    if (r == 0) out[2 * B * K + b * C + c] = sq / (float)(K * R);
}

// ---------------------------------------------------------------------------
// Kernel C (stream 0, starts at t=0): zero M with M_kernel's PROVEN layout —
// grid (128, B), 256 threads, 16 contiguous rows (128 KB) per block.
// ---------------------------------------------------------------------------
__global__ __launch_bounds__(256)
void zero_kernel(float* __restrict__ outM) {
    const int b    = blockIdx.y;
    const int tile = blockIdx.x;    // 16 rows per tile
    const int tid  = threadIdx.x;

    float4* out4 = reinterpret_cast<float4*>(outM);
    const float4 z = make_float4(0.f, 0.f, 0.f, 0.f);
    #pragma unroll
    for (int ir = 0; ir < 16; ir++) {
        const size_t base = ((size_t)b * N + tile * 16 + ir) * (N / 4);
        __stcs(&out4[base + tid], z);
        __stcs(&out4[base + tid + 256], z);
    }
    asm volatile("griddepcontrol.launch_dependents;");
}

// ---------------------------------------------------------------------------
// Kernel D (stream 0, PDL after zero, event after topk): rewrite the 64
// nonzero rows per batch as FULL contiguous 8 KB rows (no RMW sectors).
// grid (4, B) x 512 threads; block handles 16 topk entries; one float4/thread/row.
// ---------------------------------------------------------------------------
__global__ __launch_bounds__(512)
void rows_kernel(float* __restrict__ outM) {
    __shared__ float s_pv[N];
    __shared__ float s_vals[16];
    __shared__ int   s_idx[16];
    const int b    = blockIdx.y;
    const int tile = blockIdx.x;    // 16 topk entries per block
    const int tid  = threadIdx.x;

    if (tid < 16) {
        s_vals[tid] = g_vals[b * K + tile * 16 + tid];
        s_idx[tid]  = g_idx [b * K + tile * 16 + tid];
    }
    const float4* pv4 = reinterpret_cast<const float4*>(g_pv + b * N);
    float4* s4 = reinterpret_cast<float4*>(s_pv);
    s4[tid] = pv4[tid];             // N/4 = 512 = blockDim
    __syncthreads();

    // zero_kernel's stores must be complete before these rows are overwritten.
    asm volatile("griddepcontrol.wait;" ::: "memory");

    float4* out4 = reinterpret_cast<float4*>(outM);
    const float4 p = s4[tid];
    #pragma unroll
    for (int ir = 0; ir < 16; ir++) {
        const float v = s_vals[ir];
        const size_t base = ((size_t)b * N + s_idx[ir]) * (N / 4);
        __stcs(&out4[base + tid], make_float4(v * p.x, v * p.y, v * p.z, v * p.w));
    }
}

// Side stream + events (host resources only — no device memory).
static cudaStream_t g_s_side;
static cudaEvent_t  g_ev_fork, g_ev_topk, g_ev_side;
struct _StreamInit {
    _StreamInit() {
        cudaStreamCreateWithFlags(&g_s_side, cudaStreamNonBlocking);
        cudaEventCreateWithFlags(&g_ev_fork, cudaEventDisableTiming);
        cudaEventCreateWithFlags(&g_ev_topk, cudaEventDisableTiming);
        cudaEventCreateWithFlags(&g_ev_side, cudaEventDisableTiming);
    }
};
static _StreamInit g_stream_init;

extern "C" void kernel_launch(void* const* d_in, const int* in_sizes, int n_in,
                              void* d_out, int out_size) {
    const float* acc = (const float*)d_in[0];   // [B, N] float32
    const float* U   = (const float*)d_in[1];   // [C, N, R] float32
    float* out  = (float*)d_out;
    float* outM = out + 3 * B * K;

    // Legal capture fork BEFORE zero so the side stream has no dep on the fill.
    cudaEventRecord(g_ev_fork, (cudaStream_t)0);
    cudaStreamWaitEvent(g_s_side, g_ev_fork, 0);

    // Stream 0: big zero fill starts immediately.
    zero_kernel<<<dim3(128, B), 256>>>(outM);

    // Side stream: topk -> frob, concurrent with zero_kernel.
    topk_kernel<<<B, 1024, 0, g_s_side>>>(acc, out);
    cudaEventRecord(g_ev_topk, g_s_side);
    frob_kernel<<<dim3(C, B), 32, 0, g_s_side>>>(U, out);
    cudaEventRecord(g_ev_side, g_s_side);

    // Stream 0: rows after zero (PDL) and after topk (event).
    cudaStreamWaitEvent((cudaStream_t)0, g_ev_topk, 0);
    cudaLaunchConfig_t cfg = {};
    cfg.gridDim  = dim3(4, B);
    cfg.blockDim = dim3(512);
    cfg.dynamicSmemBytes = 0;
    cfg.stream = (cudaStream_t)0;
    cudaLaunchAttribute attr[1];
    attr[0].id = cudaLaunchAttributeProgrammaticStreamSerialization;
    attr[0].val.programmaticStreamSerializationAllowed = 1;
    cfg.attrs = attr;
    cfg.numAttrs = 1;
    cudaLaunchKernelEx(&cfg, rows_kernel, outM);

    // Join frob into stream 0.
    cudaStreamWaitEvent((cudaStream_t)0, g_ev_side, 0);
}

// round 12
// speedup vs baseline: 1.0637x; 1.0596x over previous
#include <cuda_runtime.h>

typedef unsigned long long u64;
typedef unsigned int u32;

#define B 32
#define N 2048
#define C 64
#define R 32
#define K 64

__device__ float g_pv[B * N];           // dense top-k vector per batch
__device__ float g_vals[B * K];
__device__ int   g_idx[B * K];
__device__ u64   g_part[B * 8 * 64];    // per-chunk top-64 sorted lists (8 chunks)

// Monotone key: descending value, ascending index, as one u64 (bigger = first).
__device__ __forceinline__ u64 make_key(float v, int idx) {
    u32 u = __float_as_uint(v);
    u = (u & 0x80000000u) ? ~u : (u | 0x80000000u);   // order-preserving f32->u32
    return ((u64)u << 32) | (u32)(N - 1 - idx);       // low word: smaller idx wins
}

// compare-exchange on packed keys; partner differs in lane bit j
__device__ __forceinline__ void cmpx64(u64& k, int j, bool desc) {
    u64 o = __shfl_xor_sync(0xffffffffu, k, j);
    bool keep_big = (((threadIdx.x & 31) & j) == 0) == desc;
    k = ((k > o) == keep_big) ? k : o;
}

// warp-level: sort 64 keys (2 per lane) descending
__device__ __forceinline__ void warp_sort64(u64& k0, u64& k1) {
    const int lane = threadIdx.x & 31;
    #pragma unroll
    for (int k = 2; k <= 32; k <<= 1) {
        #pragma unroll
        for (int j = k >> 1; j >= 1; j >>= 1) {
            cmpx64(k0, j, ((lane)      & k) == 0);
            cmpx64(k1, j, ((lane + 32) & k) == 0);
        }
    }
    if (!(k0 > k1)) { u64 t = k0; k0 = k1; k1 = t; }
    #pragma unroll
    for (int j = 16; j >= 1; j >>= 1) { cmpx64(k0, j, true); cmpx64(k1, j, true); }
}

// warp-level: top-64 of two sorted-desc 64-lists; result sorted-desc in a0/a1
__device__ __forceinline__ void warp_merge64(u64& a0, u64& a1, u64 b0, u64 b1) {
    u64 m0 = __shfl_xor_sync(0xffffffffu, b1, 31);   // B[63-e] for e=lane
    u64 m1 = __shfl_xor_sync(0xffffffffu, b0, 31);   // B[63-e] for e=lane+32
    if (m0 > a0) a0 = m0;
    if (m1 > a1) a1 = m1;
    if (!(a0 > a1)) { u64 t = a0; a0 = a1; a1 = t; }
    #pragma unroll
    for (int j = 16; j >= 1; j >>= 1) { cmpx64(a0, j, true); cmpx64(a1, j, true); }
}

// ---------------------------------------------------------------------------
// Stage 1: grid (8, B) x 128 thr. Block sorts ONE 256-elem chunk -> top-64.
// 8 chunks x 256 = N = 2048 exactly. Also zeroes pv (each thread zeros 2).
// ---------------------------------------------------------------------------
__global__ __launch_bounds__(128)
void topk_part(const float* __restrict__ acc) {
    __shared__ u64 sk[256];
    const int b    = blockIdx.y;
    const int c    = blockIdx.x;          // chunk 0..7
    const int tid  = threadIdx.x;
    const int lane = tid & 31;
    const int w    = tid >> 5;            // warp 0..3

    // zero pv: 8 blocks x 128 threads x 2 = 2048 per batch
    g_pv[b * N + c * 128 + tid]        = 0.0f;
    g_pv[b * N + 1024 + c * 128 + tid] = 0.0f;

    const float* row = acc + b * N + c * 256;
    const int base = c * 256 + w * 64;
    u64 k0 = make_key(row[w * 64 + lane],      base + lane);
    u64 k1 = make_key(row[w * 64 + 32 + lane], base + 32 + lane);
    warp_sort64(k0, k1);

    sk[w * 64 + lane]      = k0;
    sk[w * 64 + 32 + lane] = k1;
    __syncthreads();

    // 2 merge rounds: 4 lists -> 1
    u64 f0 = 0, f1 = 0;
    #pragma unroll
    for (int t = 0; t < 2; t++) {
        const int nw = 2 >> t;            // 2, 1
        if (w < nw) {
            const int la = 2 * w, lb = 2 * w + 1;
            u64 a0 = sk[la * 64 + lane];
            u64 a1 = sk[la * 64 + 32 + lane];
            u64 b0 = sk[lb * 64 + lane];
            u64 b1 = sk[lb * 64 + 32 + lane];
            warp_merge64(a0, a1, b0, b1);
            if (t < 1) {
                sk[w * 64 + lane]      = a0;
                sk[w * 64 + 32 + lane] = a1;
            } else { f0 = a0; f1 = a1; }
        }
        if (t < 1) __syncthreads();
    }

    if (w == 0) {
        g_part[(b * 8 + c) * 64 + lane]      = f0;
        g_part[(b * 8 + c) * 64 + 32 + lane] = f1;
    }
    asm volatile("griddepcontrol.launch_dependents;");
}

// ---------------------------------------------------------------------------
// Stage 2: grid B x 256 thr (8 warps). Merge 8 sorted lists -> final top-64;
// emit outputs, pv scatter, g_vals/g_idx.
// ---------------------------------------------------------------------------
__global__ __launch_bounds__(256)
void topk_merge(float* __restrict__ out) {
    asm volatile("griddepcontrol.wait;" ::: "memory");
    __shared__ u64 sk[512];
    const int b    = blockIdx.x;
    const int tid  = threadIdx.x;
    const int lane = tid & 31;
    const int w    = tid >> 5;            // warp 0..7

    sk[w * 64 + lane]      = g_part[(b * 8 + w) * 64 + lane];
    sk[w * 64 + 32 + lane] = g_part[(b * 8 + w) * 64 + 32 + lane];
    __syncthreads();

    // 3 merge rounds: 8 -> 1
    u64 f0 = 0, f1 = 0;
    #pragma unroll
    for (int t = 0; t < 3; t++) {
        const int nw = 4 >> t;            // 4, 2, 1
        if (w < nw) {
            const int la = 2 * w, lb = 2 * w + 1;
            u64 a0 = sk[la * 64 + lane];
            u64 a1 = sk[la * 64 + 32 + lane];
            u64 b0 = sk[lb * 64 + lane];
            u64 b1 = sk[lb * 64 + 32 + lane];
            warp_merge64(a0, a1, b0, b1);
            if (t < 2) {
                sk[w * 64 + lane]      = a0;
                sk[w * 64 + 32 + lane] = a1;
            } else { f0 = a0; f1 = a1; }
        }
        if (t < 2) __syncthreads();
    }

    if (w == 0) {
        #pragma unroll
        for (int h = 0; h < 2; h++) {
            u64 kk = h ? f1 : f0;
            int pos = lane + h * 32;
            int id = (N - 1) - (int)(kk & 0xffffffffu);
            u32 hu = (u32)(kk >> 32);
            u32 fb = (hu & 0x80000000u) ? (hu ^ 0x80000000u) : ~hu;
            float v = __uint_as_float(fb);
            out[b * K + pos]         = v;           // topk_vals
            out[B * K + b * K + pos] = (float)id;   // topk_idx
            g_vals[b * K + pos] = v;
            g_idx [b * K + pos] = id;
            g_pv  [b * N + id]  = v;
        }
    }
    asm volatile("griddepcontrol.launch_dependents;");
}

// ---------------------------------------------------------------------------
// frob (side stream, concurrent with M): one warp per (channel, batch).
// ---------------------------------------------------------------------------
__global__ __launch_bounds__(32)
void frob_kernel(const float* __restrict__ U, float* __restrict__ out) {
    const int c = blockIdx.x;
    const int b = blockIdx.y;
    const int r = threadIdx.x;

    float v0 = g_vals[b * K + r];
    float v1 = g_vals[b * K + 32 + r];
    int   i0 = g_idx [b * K + r];
    int   i1 = g_idx [b * K + 32 + r];

    const float* Uc = U + (size_t)c * N * R;
    float au = 0.0f;
    #pragma unroll
    for (int k = 0; k < 32; k++) {
        float vk = __shfl_sync(0xffffffffu, v0, k);
        int   ik = __shfl_sync(0xffffffffu, i0, k);
        au = fmaf(vk, __ldg(Uc + (size_t)ik * R + r), au);
    }
    #pragma unroll
    for (int k = 0; k < 32; k++) {
        float vk = __shfl_sync(0xffffffffu, v1, k);
        int   ik = __shfl_sync(0xffffffffu, i1, k);
        au = fmaf(vk, __ldg(Uc + (size_t)ik * R + r), au);
    }

    float sq = au * au;
    #pragma unroll
    for (int o = 16; o > 0; o >>= 1)
        sq += __shfl_xor_sync(0xffffffffu, sq, o);
    if (r == 0) out[2 * B * K + b * C + c] = sq / (float)(K * R);
}

// ---------------------------------------------------------------------------
// M[b,i,j] = pv[b][i] * pv[b][j] — proven store-roofline kernel (76.8us),
// PDL-gated on topk_merge. Do not touch the store loop.
// ---------------------------------------------------------------------------
__global__ __launch_bounds__(256)
void M_kernel(float* __restrict__ outM) {
    __shared__ float s_pv[N];
    const int b    = blockIdx.y;
    const int tile = blockIdx.x;
    const int tid  = threadIdx.x;

    asm volatile("griddepcontrol.wait;" ::: "memory");

    const float4* pv4 = reinterpret_cast<const float4*>(g_pv + b * N);
    float4* s4 = reinterpret_cast<float4*>(s_pv);
    for (int q = tid; q < N / 4; q += 256) s4[q] = pv4[q];
    __syncthreads();

    float4* out4 = reinterpret_cast<float4*>(outM);
    #pragma unroll
    for (int ir = 0; ir < 16; ir++) {
        const int i = tile * 16 + ir;
        const float pvi = s_pv[i];
        const size_t base = ((size_t)b * N + i) * (N / 4);
        #pragma unroll
        for (int jj = 0; jj < 2; jj++) {
            const int j4 = tid + jj * 256;
            float4 v = s4[j4];
            float4 o = make_float4(pvi * v.x, pvi * v.y, pvi * v.z, pvi * v.w);
            __stcs(&out4[base + j4], o);
        }
    }
}

// Side stream + events (host resources only — no device memory).
static cudaStream_t g_s_side;
static cudaEvent_t  g_ev_topk, g_ev_side;
struct _StreamInit {
    _StreamInit() {
        cudaStreamCreateWithFlags(&g_s_side, cudaStreamNonBlocking);
        cudaEventCreateWithFlags(&g_ev_topk, cudaEventDisableTiming);
        cudaEventCreateWithFlags(&g_ev_side, cudaEventDisableTiming);
    }
};
static _StreamInit g_stream_init;

static void launch_pdl(void* fn, dim3 grid, dim3 block, void** args) {
    cudaLaunchConfig_t cfg = {};
    cfg.gridDim  = grid;
    cfg.blockDim = block;
    cfg.dynamicSmemBytes = 0;
    cfg.stream = (cudaStream_t)0;
    cudaLaunchAttribute attr[1];
    attr[0].id = cudaLaunchAttributeProgrammaticStreamSerialization;
    attr[0].val.programmaticStreamSerializationAllowed = 1;
    cfg.attrs = attr;
    cfg.numAttrs = 1;
    cudaLaunchKernelExC(&cfg, fn, args);
}

extern "C" void kernel_launch(void* const* d_in, const int* in_sizes, int n_in,
                              void* d_out, int out_size) {
    const float* acc = (const float*)d_in[0];   // [B, N] float32
    const float* U   = (const float*)d_in[1];   // [C, N, R] float32
    float* out  = (float*)d_out;
    float* outM = out + 3 * B * K;

    // Stage 1 (normal launch): 256 blocks, spreads shuffle work chip-wide.
    topk_part<<<dim3(8, B), 128>>>(acc);

    // Stage 2 (PDL on stage 1)
    {
        void* args[] = { (void*)&out };
        launch_pdl((void*)topk_merge, dim3(B), dim3(256), args);
    }

    // Fork: frob concurrent with M, after topk_merge.
    cudaEventRecord(g_ev_topk, (cudaStream_t)0);
    cudaStreamWaitEvent(g_s_side, g_ev_topk, 0);
    frob_kernel<<<dim3(C, B), 32, 0, g_s_side>>>(U, out);
    cudaEventRecord(g_ev_side, g_s_side);

    // M (PDL on topk_merge)
    {
        void* args[] = { (void*)&outM };
        launch_pdl((void*)M_kernel, dim3(N / 16, B), dim3(256), args);
    }

    // Join frob into stream 0.
    cudaStreamWaitEvent((cudaStream_t)0, g_ev_side, 0);
}